// round 1
// baseline (speedup 1.0000x reference)
#include <cuda_runtime.h>
#include <cstdint>

#define BATCH 2
#define SEQ 2048
#define DIN 2048
#define DOUT 2048
#define TOPK 2

#define BM 128
#define BN 128
#define BK 32
#define NTHREADS 256
#define LDA 36           // 128B-row + pad: A-frag loads provably conflict-free
#define LDB 132

#define A_BUF_FLOATS (BM * LDA)                        // 4608
#define B_BUF_FLOATS (BK * LDB)                        // 4224
#define SMEM_B_OFF   (2 * A_BUF_FLOATS)                // 9216
#define SMEM_BIAS_OFF (SMEM_B_OFF + 2 * B_BUF_FLOATS)  // 17664
#define SMEM_FLOATS  (SMEM_BIAS_OFF + BN)              // 17792
#define SMEM_BYTES   (SMEM_FLOATS * 4)                 // 71168

// Scratch (no cudaMalloc allowed): per-batch superposed weights (tf32-rounded)
// and tf32-rounded activations.
__device__ __align__(16) float g_wsel[(size_t)BATCH * DIN * DOUT];
__device__ __align__(16) float g_xc[(size_t)BATCH * SEQ * DIN];

__device__ __forceinline__ float to_tf32(float v) {
    uint32_t u;
    asm("cvt.rna.tf32.f32 %0, %1;" : "=r"(u) : "f"(v));
    return __uint_as_float(u);
}

__device__ __forceinline__ void mma_tf32(float c[4], const float a[4], const float b[2]) {
    const uint32_t* A = reinterpret_cast<const uint32_t*>(a);
    const uint32_t* B = reinterpret_cast<const uint32_t*>(b);
    asm volatile(
        "mma.sync.aligned.m16n8k8.row.col.f32.tf32.tf32.f32 "
        "{%0,%1,%2,%3}, {%4,%5,%6,%7}, {%8,%9}, {%0,%1,%2,%3};\n"
        : "+f"(c[0]), "+f"(c[1]), "+f"(c[2]), "+f"(c[3])
        : "r"(A[0]), "r"(A[1]), "r"(A[2]), "r"(A[3]), "r"(B[0]), "r"(B[1]));
}

// ---------------------------------------------------------------------------
// Kernel 1: w_sel[b] = tf32(p0*W[i0] + p1*W[i1]); xc = tf32(x)
// x is (B,S,H,Dh) contiguous == (B,S,DIN) merged view, same element count as wsel.
// ---------------------------------------------------------------------------
__global__ void build_kernel(const float* __restrict__ x,
                             const int* __restrict__ sel_idx,
                             const float* __restrict__ sel_prob,
                             const float* __restrict__ weight) {
    const int n4 = (DIN * DOUT) / 4;        // per-batch float4 count = 1048576
    const int total = BATCH * n4;
    const float4* x4 = (const float4*)x;
    const float4* w4 = (const float4*)weight;
    float4* ws4 = (float4*)g_wsel;
    float4* xc4 = (float4*)g_xc;
    for (int i = blockIdx.x * blockDim.x + threadIdx.x; i < total;
         i += gridDim.x * blockDim.x) {
        const int b = i / n4;
        const int e = i - b * n4;
        const int i0 = sel_idx[b * TOPK + 0];
        const int i1 = sel_idx[b * TOPK + 1];
        const float p0 = sel_prob[b * TOPK + 0];
        const float p1 = sel_prob[b * TOPK + 1];
        const float4 wa = w4[(size_t)i0 * n4 + e];
        const float4 wb = w4[(size_t)i1 * n4 + e];
        float4 r;
        r.x = to_tf32(p0 * wa.x + p1 * wb.x);
        r.y = to_tf32(p0 * wa.y + p1 * wb.y);
        r.z = to_tf32(p0 * wa.z + p1 * wb.z);
        r.w = to_tf32(p0 * wa.w + p1 * wb.w);
        ws4[i] = r;
        const float4 xv = x4[i];
        float4 xr;
        xr.x = to_tf32(xv.x);
        xr.y = to_tf32(xv.y);
        xr.z = to_tf32(xv.z);
        xr.w = to_tf32(xv.w);
        xc4[i] = xr;
    }
}

// ---------------------------------------------------------------------------
// Kernel 2: out[b] = xc[b] (SEQ x DIN) @ wsel[b] (DIN x DOUT) + bias_sel[b]
// 128x128x32 tiles, double-buffered cp.async, 8 warps of 64x32 (m16n8k8 tf32).
// ---------------------------------------------------------------------------
__global__ void __launch_bounds__(NTHREADS, 2)
gemm_kernel(const int* __restrict__ sel_idx,
            const float* __restrict__ sel_prob,
            const float* __restrict__ bias,
            float* __restrict__ out) {
    extern __shared__ float smem[];
    const int tid = threadIdx.x;
    const int warp = tid >> 5;
    const int lane = tid & 31;
    const int gp = lane >> 2;       // group id 0..7
    const int tg = lane & 3;        // thread-in-group 0..3
    const int warp_m = warp >> 2;   // 0..1
    const int warp_n = warp & 3;    // 0..3
    const int bz = blockIdx.z;
    const int m0 = blockIdx.y * BM;
    const int n0 = blockIdx.x * BN;

    const float* xbase = g_xc + (size_t)bz * SEQ * DIN + (size_t)m0 * DIN;
    const float* wbase = g_wsel + (size_t)bz * DIN * DOUT + n0;

    // bias superposition for this block's output columns
    if (tid < BN) {
        const int i0 = sel_idx[bz * TOPK + 0];
        const int i1 = sel_idx[bz * TOPK + 1];
        const float p0 = sel_prob[bz * TOPK + 0];
        const float p1 = sel_prob[bz * TOPK + 1];
        smem[SMEM_BIAS_OFF + tid] =
            p0 * bias[i0 * DOUT + n0 + tid] + p1 * bias[i1 * DOUT + n0 + tid];
    }

    float acc[4][4][4];
#pragma unroll
    for (int mi = 0; mi < 4; ++mi)
#pragma unroll
        for (int ni = 0; ni < 4; ++ni)
#pragma unroll
            for (int r = 0; r < 4; ++r) acc[mi][ni][r] = 0.0f;

    const uint32_t sbase = (uint32_t)__cvta_generic_to_shared(smem);

    auto issue_stage = [&](int kt, int buf) {
        const float* ga = xbase + kt * BK;
#pragma unroll
        for (int i = 0; i < 4; ++i) {
            const int j = tid + i * NTHREADS;          // 0..1023
            const int row = j >> 3;                    // 0..127
            const int c4 = (j & 7) << 2;               // 0..28
            const uint32_t s =
                sbase + (uint32_t)((buf * A_BUF_FLOATS + row * LDA + c4) * 4);
            asm volatile("cp.async.cg.shared.global [%0], [%1], 16;\n"
                         :: "r"(s), "l"(ga + (size_t)row * DIN + c4));
        }
        const float* gb = wbase + (size_t)(kt * BK) * DOUT;
#pragma unroll
        for (int i = 0; i < 4; ++i) {
            const int j = tid + i * NTHREADS;
            const int row = j >> 5;                    // 0..31
            const int c4 = (j & 31) << 2;              // 0..124
            const uint32_t s =
                sbase + (uint32_t)((SMEM_B_OFF + buf * B_BUF_FLOATS + row * LDB + c4) * 4);
            asm volatile("cp.async.cg.shared.global [%0], [%1], 16;\n"
                         :: "r"(s), "l"(gb + (size_t)row * DOUT + c4));
        }
        asm volatile("cp.async.commit_group;\n");
    };

    const int KT = DIN / BK;   // 64
    issue_stage(0, 0);

    for (int kt = 0; kt < KT; ++kt) {
        const int buf = kt & 1;
        if (kt + 1 < KT) {
            issue_stage(kt + 1, buf ^ 1);
            asm volatile("cp.async.wait_group 1;\n" ::: "memory");
        } else {
            asm volatile("cp.async.wait_group 0;\n" ::: "memory");
        }
        __syncthreads();

        const float* sA = smem + buf * A_BUF_FLOATS + (warp_m * 64 + gp) * LDA;
        const float* sB = smem + SMEM_B_OFF + buf * B_BUF_FLOATS + warp_n * 32 + gp;
#pragma unroll
        for (int kk = 0; kk < BK / 8; ++kk) {
            float a[4][4], bb[4][2];
            const int k8 = kk * 8 + tg;
#pragma unroll
            for (int mi = 0; mi < 4; ++mi) {
                const float* p = sA + mi * 16 * LDA + k8;
                a[mi][0] = p[0];            // (row g,   col tg)
                a[mi][1] = p[8 * LDA];      // (row g+8, col tg)
                a[mi][2] = p[4];            // (row g,   col tg+4)
                a[mi][3] = p[8 * LDA + 4];  // (row g+8, col tg+4)
            }
#pragma unroll
            for (int ni = 0; ni < 4; ++ni) {
                const float* p = sB + k8 * LDB + ni * 8;
                bb[ni][0] = p[0];           // (k tg,   n gp)
                bb[ni][1] = p[4 * LDB];     // (k tg+4, n gp)
            }
#pragma unroll
            for (int mi = 0; mi < 4; ++mi)
#pragma unroll
                for (int ni = 0; ni < 4; ++ni)
                    mma_tf32(acc[mi][ni], a[mi], bb[ni]);
        }
        __syncthreads();
    }

    // Epilogue: acc + bias_sel, float2 stores
    float* outb = out + (size_t)bz * SEQ * DOUT + (size_t)m0 * DOUT + n0;
#pragma unroll
    for (int mi = 0; mi < 4; ++mi) {
        const int r0 = warp_m * 64 + mi * 16 + gp;
#pragma unroll
        for (int ni = 0; ni < 4; ++ni) {
            const int cc = warp_n * 32 + ni * 8 + tg * 2;
            const float b0 = smem[SMEM_BIAS_OFF + cc];
            const float b1 = smem[SMEM_BIAS_OFF + cc + 1];
            const float2 v0 = make_float2(acc[mi][ni][0] + b0, acc[mi][ni][1] + b1);
            const float2 v1 = make_float2(acc[mi][ni][2] + b0, acc[mi][ni][3] + b1);
            *(float2*)(outb + (size_t)r0 * DOUT + cc) = v0;
            *(float2*)(outb + (size_t)(r0 + 8) * DOUT + cc) = v1;
        }
    }
}

extern "C" void kernel_launch(void* const* d_in, const int* in_sizes, int n_in,
                              void* d_out, int out_size) {
    const float* tensor   = (const float*)d_in[0];  // (B,S,H,Dh) fp32
    const int*   sel_idx  = (const int*)d_in[1];    // (B,TOPK) int32
    const float* sel_prob = (const float*)d_in[2];  // (B,TOPK) fp32
    const float* weight   = (const float*)d_in[3];  // (16,DIN,DOUT) fp32
    const float* bias     = (const float*)d_in[4];  // (16,DOUT) fp32
    float* out = (float*)d_out;

    build_kernel<<<2048, 256>>>(tensor, sel_idx, sel_prob, weight);

    cudaFuncSetAttribute(gemm_kernel,
                         cudaFuncAttributeMaxDynamicSharedMemorySize, SMEM_BYTES);
    dim3 grid(DOUT / BN, SEQ / BM, BATCH);
    gemm_kernel<<<grid, NTHREADS, SMEM_BYTES>>>(sel_idx, sel_prob, bias, out);
}

// round 4
// speedup vs baseline: 1.1933x; 1.1933x over previous
#include <cuda_runtime.h>
#include <cstdint>

#define BATCH 2
#define SEQ 2048
#define DIN 2048
#define DOUT 2048
#define TOPK 2

#define BM 128
#define BN 128
#define BK 32
#define NC (DIN / BK)          // 64 k-chunks
#define NSTAGE 3
#define NTHREADS 256

// stage = A(4096 floats) + B(4096 floats) = 32KB
#define STAGE_FLOATS 8192
#define A_STAGE_FLOATS 4096
#define SMEM_BIAS_F (NSTAGE * STAGE_FLOATS)            // 24576
#define SMEM_FLOATS (SMEM_BIAS_F + BN)                 // 24704
#define SMEM_BYTES  (SMEM_FLOATS * 4)                  // 98816

// Fragment-packed scratch (__device__ globals: allocation-guard-safe).
// A: [b][kslab(256)][mtile(128)][lane(32)][4]   (float4 per lane)
// B: [b][kslab(256)][ntile(256)][lane(32)][2]   (float2 per lane)
__device__ __align__(16) float g_xa[(size_t)BATCH * SEQ * DIN];
__device__ __align__(16) float g_wb[(size_t)BATCH * DIN * DOUT];

__device__ __forceinline__ float to_tf32(float v) {
    uint32_t u;
    asm("cvt.rna.tf32.f32 %0, %1;" : "=r"(u) : "f"(v));
    return __uint_as_float(u);
}

__device__ __forceinline__ void mma_tf32(float c[4], const float a[4], const float b[2]) {
    const uint32_t* A = reinterpret_cast<const uint32_t*>(a);
    const uint32_t* B = reinterpret_cast<const uint32_t*>(b);
    asm volatile(
        "mma.sync.aligned.m16n8k8.row.col.f32.tf32.tf32.f32 "
        "{%0,%1,%2,%3}, {%4,%5,%6,%7}, {%8,%9}, {%0,%1,%2,%3};\n"
        : "+f"(c[0]), "+f"(c[1]), "+f"(c[2]), "+f"(c[3])
        : "r"(A[0]), "r"(A[1]), "r"(A[2]), "r"(A[3]), "r"(B[0]), "r"(B[1]));
}

// ---------------------------------------------------------------------------
// Kernel A: pack x into A-fragment layout (tf32-rounded).
// For float4 index f: lane=f&31, mtile=(f>>5)&127, kslab=(f>>12)&255, b=f>>20.
// slots: (gp,tg),(gp+8,tg),(gp,tg+4),(gp+8,tg+4) within the 16x8 tile.
// ---------------------------------------------------------------------------
__global__ void pack_x_kernel(const float* __restrict__ x) {
    const int total = BATCH << 20;    // float4 count
    float4* o4 = (float4*)g_xa;
    for (int f = blockIdx.x * blockDim.x + threadIdx.x; f < total;
         f += gridDim.x * blockDim.x) {
        const int lane = f & 31;
        const int mtile = (f >> 5) & 127;
        const int kslab = (f >> 12) & 255;
        const int b = f >> 20;
        const int gp = lane >> 2, tg = lane & 3;
        const size_t base = ((size_t)b * SEQ + mtile * 16 + gp) * DIN + kslab * 8 + tg;
        float4 r;
        r.x = to_tf32(x[base]);
        r.y = to_tf32(x[base + 8 * DIN]);
        r.z = to_tf32(x[base + 4]);
        r.w = to_tf32(x[base + 8 * DIN + 4]);
        o4[f] = r;
    }
}

// ---------------------------------------------------------------------------
// Kernel B: superpose selected banks and pack into B-fragment layout.
// For float2 index f: lane=f&31, ntile=(f>>5)&255, kslab=(f>>13)&255, b=f>>21.
// slots: (k=tg, n=gp), (k=tg+4, n=gp).
// ---------------------------------------------------------------------------
__global__ void pack_w_kernel(const int* __restrict__ sel_idx,
                              const float* __restrict__ sel_prob,
                              const float* __restrict__ weight) {
    const int total = BATCH << 21;    // float2 count
    float2* o2 = (float2*)g_wb;
    for (int f = blockIdx.x * blockDim.x + threadIdx.x; f < total;
         f += gridDim.x * blockDim.x) {
        const int lane = f & 31;
        const int ntile = (f >> 5) & 255;
        const int kslab = (f >> 13) & 255;
        const int b = f >> 21;
        const int gp = lane >> 2, tg = lane & 3;
        const int i0 = sel_idx[b * TOPK + 0];
        const int i1 = sel_idx[b * TOPK + 1];
        const float p0 = sel_prob[b * TOPK + 0];
        const float p1 = sel_prob[b * TOPK + 1];
        const size_t e0 = (size_t)(kslab * 8 + tg) * DOUT + ntile * 8 + gp;
        const float* w0 = weight + (size_t)i0 * DIN * DOUT;
        const float* w1 = weight + (size_t)i1 * DIN * DOUT;
        float2 r;
        r.x = to_tf32(p0 * w0[e0] + p1 * w1[e0]);
        r.y = to_tf32(p0 * w0[e0 + 4 * DOUT] + p1 * w1[e0 + 4 * DOUT]);
        o2[f] = r;
    }
}

// ---------------------------------------------------------------------------
// Kernel C: fragment-packed tf32 mma.sync GEMM + fused bias.
// 8 warps: warp_m(2) x warp_n(4), warp tile 64x32, 3-stage cp.async.
// ---------------------------------------------------------------------------
__global__ void __launch_bounds__(NTHREADS, 2)
gemm_kernel(const int* __restrict__ sel_idx,
            const float* __restrict__ sel_prob,
            const float* __restrict__ bias,
            float* __restrict__ out) {
    extern __shared__ float smem[];
    const int tid = threadIdx.x;
    const int warp = tid >> 5;
    const int lane = tid & 31;
    const int gp = lane >> 2;
    const int tg = lane & 3;
    const int warp_m = warp >> 2;   // 0..1
    const int warp_n = warp & 3;    // 0..3
    const int bz = blockIdx.z;
    const int mt0 = blockIdx.y * (BM / 16);   // base mtile (8 per block)
    const int nt0 = blockIdx.x * (BN / 8);    // base ntile (16 per block)

    if (tid < BN) {
        const int i0 = sel_idx[bz * TOPK + 0];
        const int i1 = sel_idx[bz * TOPK + 1];
        const float p0 = sel_prob[bz * TOPK + 0];
        const float p1 = sel_prob[bz * TOPK + 1];
        const int n0 = blockIdx.x * BN;
        smem[SMEM_BIAS_F + tid] =
            p0 * bias[i0 * DOUT + n0 + tid] + p1 * bias[i1 * DOUT + n0 + tid];
    }

    float acc[4][4][4];
#pragma unroll
    for (int mi = 0; mi < 4; ++mi)
#pragma unroll
        for (int ni = 0; ni < 4; ++ni)
#pragma unroll
            for (int r = 0; r < 4; ++r) acc[mi][ni][r] = 0.0f;

    const uint32_t sbase = (uint32_t)__cvta_generic_to_shared(smem);
    const float4* gA = (const float4*)g_xa + ((size_t)bz << 20);
    const float4* gB = (const float4*)g_wb + ((size_t)bz << 20);

    // fill stage s with chunk c: A 1024 float4 + B 1024 float4, fully contiguous runs
    auto fill = [&](int s, int c) {
#pragma unroll
        for (int i = 0; i < 4; ++i) {
            const int j = tid + i * NTHREADS;        // 0..1023
            const int ks = j >> 8;                   // kslab local 0..3
            const int rem = j & 255;
            const int gks = c * 4 + ks;
            // A: [gks][mt0 + (rem>>5)][rem&31]
            const size_t fa = ((size_t)gks << 12) + ((size_t)(mt0 + (rem >> 5)) << 5) + (rem & 31);
            const uint32_t da = sbase + (uint32_t)((s * STAGE_FLOATS + j * 4) * 4);
            asm volatile("cp.async.cg.shared.global [%0], [%1], 16;"
                         :: "r"(da), "l"(gA + fa));
            // B: [gks][nt0*16B-run]: float4 index = (gks<<12) + (nt0<<4) + rem
            const size_t fb = ((size_t)gks << 12) + ((size_t)nt0 << 4) + rem;
            const uint32_t db = sbase + (uint32_t)((s * STAGE_FLOATS + A_STAGE_FLOATS + j * 4) * 4);
            asm volatile("cp.async.cg.shared.global [%0], [%1], 16;"
                         :: "r"(db), "l"(gB + fb));
        }
        asm volatile("cp.async.commit_group;");
    };

    fill(0, 0);
    fill(1, 1);
    fill(2, 2);

    for (int c = 0; c < NC; ++c) {
        const int s = c % NSTAGE;
        const int pend = (NC - 1 - c) < 2 ? (NC - 1 - c) : 2;
        if (pend == 2)      asm volatile("cp.async.wait_group 2;" ::: "memory");
        else if (pend == 1) asm volatile("cp.async.wait_group 1;" ::: "memory");
        else                asm volatile("cp.async.wait_group 0;" ::: "memory");
        __syncthreads();

        const float* As = smem + s * STAGE_FLOATS;
        const float* Bs = As + A_STAGE_FLOATS;
#pragma unroll
        for (int ks = 0; ks < 4; ++ks) {
            float a[4][4], bb[4][2];
#pragma unroll
            for (int mi = 0; mi < 4; ++mi) {
                const float4 v = *(const float4*)(As + ks * 1024 +
                                                  (warp_m * 4 + mi) * 128 + lane * 4);
                a[mi][0] = v.x; a[mi][1] = v.y; a[mi][2] = v.z; a[mi][3] = v.w;
            }
#pragma unroll
            for (int ni = 0; ni < 4; ++ni) {
                const float2 v = *(const float2*)(Bs + ks * 1024 +
                                                  (warp_n * 4 + ni) * 64 + lane * 2);
                bb[ni][0] = v.x; bb[ni][1] = v.y;
            }
#pragma unroll
            for (int mi = 0; mi < 4; ++mi)
#pragma unroll
                for (int ni = 0; ni < 4; ++ni)
                    mma_tf32(acc[mi][ni], a[mi], bb[ni]);
        }
        __syncthreads();
        if (c + NSTAGE < NC) fill(s, c + NSTAGE);
    }

    // epilogue: acc + bias, float2 stores
    const int m0 = blockIdx.y * BM;
    const int n0 = blockIdx.x * BN;
    float* outb = out + (size_t)bz * SEQ * DOUT + (size_t)m0 * DOUT + n0;
#pragma unroll
    for (int mi = 0; mi < 4; ++mi) {
        const int r0 = warp_m * 64 + mi * 16 + gp;
#pragma unroll
        for (int ni = 0; ni < 4; ++ni) {
            const int cc = warp_n * 32 + ni * 8 + tg * 2;
            const float b0 = smem[SMEM_BIAS_F + cc];
            const float b1 = smem[SMEM_BIAS_F + cc + 1];
            const float2 v0 = make_float2(acc[mi][ni][0] + b0, acc[mi][ni][1] + b1);
            const float2 v1 = make_float2(acc[mi][ni][2] + b0, acc[mi][ni][3] + b1);
            *(float2*)(outb + (size_t)r0 * DOUT + cc) = v0;
            *(float2*)(outb + (size_t)(r0 + 8) * DOUT + cc) = v1;
        }
    }
}

extern "C" void kernel_launch(void* const* d_in, const int* in_sizes, int n_in,
                              void* d_out, int out_size) {
    const float* tensor   = (const float*)d_in[0];  // (B,S,H,Dh) fp32
    const int*   sel_idx  = (const int*)d_in[1];    // (B,TOPK) int32
    const float* sel_prob = (const float*)d_in[2];  // (B,TOPK) fp32
    const float* weight   = (const float*)d_in[3];  // (16,DIN,DOUT) fp32
    const float* bias     = (const float*)d_in[4];  // (16,DOUT) fp32
    float* out = (float*)d_out;

    pack_x_kernel<<<2048, 256>>>(tensor);
    pack_w_kernel<<<2048, 256>>>(sel_idx, sel_prob, weight);

    cudaFuncSetAttribute(gemm_kernel,
                         cudaFuncAttributeMaxDynamicSharedMemorySize, SMEM_BYTES);
    dim3 grid(DOUT / BN, SEQ / BM, BATCH);
    gemm_kernel<<<grid, NTHREADS, SMEM_BYTES>>>(sel_idx, sel_prob, bias, out);
}

// round 6
// speedup vs baseline: 1.2349x; 1.0349x over previous
#include <cuda_runtime.h>
#include <cstdint>

#define BATCH 2
#define SEQ 2048
#define DIN 2048
#define DOUT 2048
#define TOPK 2

#define BM 128
#define BN 128
#define BK 32
#define NC (DIN / BK)          // 64 k-chunks
#define NSTAGE 3
#define NTHREADS 256

// stage = A(4096 floats) + B(4096 floats) = 32KB
#define STAGE_FLOATS 8192
#define A_STAGE_FLOATS 4096
#define SMEM_BIAS_F (NSTAGE * STAGE_FLOATS)            // 24576
#define SMEM_FLOATS (SMEM_BIAS_F + BN)                 // 24704
#define SMEM_BYTES  (SMEM_FLOATS * 4)                  // 98816

// Fragment-packed scratch (__device__ globals: allocation-guard-safe).
// A: [b][kslab(256)][mtile(128)][lane(32)][4]   (float4 per lane)
// B: [b][kslab(256)][ntile(256)][lane(32)][2]   (float2 per lane)
__device__ __align__(16) float g_xa[(size_t)BATCH * SEQ * DIN];
__device__ __align__(16) float g_wb[(size_t)BATCH * DIN * DOUT];

__device__ __forceinline__ float to_tf32(float v) {
    uint32_t u;
    asm("cvt.rna.tf32.f32 %0, %1;" : "=r"(u) : "f"(v));
    return __uint_as_float(u);
}

__device__ __forceinline__ void mma_tf32(float c[4], const float a[4], const float b[2]) {
    const uint32_t* A = reinterpret_cast<const uint32_t*>(a);
    const uint32_t* B = reinterpret_cast<const uint32_t*>(b);
    asm volatile(
        "mma.sync.aligned.m16n8k8.row.col.f32.tf32.tf32.f32 "
        "{%0,%1,%2,%3}, {%4,%5,%6,%7}, {%8,%9}, {%0,%1,%2,%3};\n"
        : "+f"(c[0]), "+f"(c[1]), "+f"(c[2]), "+f"(c[3])
        : "r"(A[0]), "r"(A[1]), "r"(A[2]), "r"(A[3]), "r"(B[0]), "r"(B[1]));
}

// ---------------------------------------------------------------------------
// Kernel A: staged pack of x into A-fragment layout (tf32-rounded).
// Block: 64 m-rows x 64 k-cols. Coalesced float4 loads -> smem -> fragment
// float4 stores (512B contiguous per warp).
// A fragment f = (b<<20)+(kslab<<12)+(mtile<<5)+lane holds
// {x[gp,tg], x[gp+8,tg], x[gp,tg+4], x[gp+8,tg+4]} of the 16x8 (m,k) tile.
// ---------------------------------------------------------------------------
__global__ void pack_x_kernel(const float* __restrict__ x) {
    __shared__ float tile[64][72];
    const int b = blockIdx.z;
    const int m0 = blockIdx.x * 64;
    const int k0 = blockIdx.y * 64;
    const int tid = threadIdx.x;
    const float* xb = x + ((size_t)b * SEQ + m0) * DIN + k0;
#pragma unroll
    for (int i = 0; i < 4; ++i) {
        const int idx = tid + i * 256;          // 1024 float4 slots
        const int r = idx >> 4;                 // m-local 0..63
        const int c4 = (idx & 15) << 2;         // k-local 0..60
        const float4 v = *(const float4*)(xb + (size_t)r * DIN + c4);
        tile[r][c4 + 0] = to_tf32(v.x);
        tile[r][c4 + 1] = to_tf32(v.y);
        tile[r][c4 + 2] = to_tf32(v.z);
        tile[r][c4 + 3] = to_tf32(v.w);
    }
    __syncthreads();
    const int warp = tid >> 5;
    const int lane = tid & 31;
    const int gp = lane >> 2, tg = lane & 3;
    float4* o4 = (float4*)g_xa;
#pragma unroll
    for (int i = 0; i < 4; ++i) {
        const int pair = warp * 4 + i;          // 0..31
        const int mt = pair >> 3;               // mtile-local 0..3
        const int ks = pair & 7;                // kslab-local 0..7
        float4 r;
        r.x = tile[mt * 16 + gp][ks * 8 + tg];
        r.y = tile[mt * 16 + gp + 8][ks * 8 + tg];
        r.z = tile[mt * 16 + gp][ks * 8 + tg + 4];
        r.w = tile[mt * 16 + gp + 8][ks * 8 + tg + 4];
        const size_t f = ((size_t)b << 20) + ((size_t)(k0 / 8 + ks) << 12) +
                         ((size_t)(m0 / 16 + mt) << 5) + lane;
        o4[f] = r;
    }
}

// ---------------------------------------------------------------------------
// Kernel B: staged superpose + pack of weights into B-fragment layout.
// Block: 64 k-rows x 64 n-cols. Coalesced float4 loads of both banks ->
// smem (pad 72: fragment reads conflict-free) -> float2 stores (256B runs).
// B fragment f = (b<<21)+(kslab<<13)+(ntile<<5)+lane holds
// {w[tg,gp], w[tg+4,gp]} of the 8x8 (k,n) tile.
// ---------------------------------------------------------------------------
__global__ void pack_w_kernel(const int* __restrict__ sel_idx,
                              const float* __restrict__ sel_prob,
                              const float* __restrict__ weight) {
    __shared__ float tile[64][72];
    const int b = blockIdx.z;
    const int k0 = blockIdx.x * 64;
    const int n0 = blockIdx.y * 64;
    const int tid = threadIdx.x;
    const int i0 = sel_idx[b * TOPK + 0];
    const int i1 = sel_idx[b * TOPK + 1];
    const float p0 = sel_prob[b * TOPK + 0];
    const float p1 = sel_prob[b * TOPK + 1];
    const float* w0 = weight + (size_t)i0 * DIN * DOUT + (size_t)k0 * DOUT + n0;
    const float* w1 = weight + (size_t)i1 * DIN * DOUT + (size_t)k0 * DOUT + n0;
#pragma unroll
    for (int i = 0; i < 4; ++i) {
        const int idx = tid + i * 256;
        const int r = idx >> 4;                 // k-local 0..63
        const int c4 = (idx & 15) << 2;         // n-local 0..60
        const float4 va = *(const float4*)(w0 + (size_t)r * DOUT + c4);
        const float4 vb = *(const float4*)(w1 + (size_t)r * DOUT + c4);
        tile[r][c4 + 0] = to_tf32(p0 * va.x + p1 * vb.x);
        tile[r][c4 + 1] = to_tf32(p0 * va.y + p1 * vb.y);
        tile[r][c4 + 2] = to_tf32(p0 * va.z + p1 * vb.z);
        tile[r][c4 + 3] = to_tf32(p0 * va.w + p1 * vb.w);
    }
    __syncthreads();
    const int warp = tid >> 5;
    const int lane = tid & 31;
    const int gp = lane >> 2, tg = lane & 3;
    float2* o2 = (float2*)g_wb;
#pragma unroll
    for (int i = 0; i < 8; ++i) {
        const int pair = warp * 8 + i;          // 0..63
        const int ks = pair >> 3;               // kslab-local 0..7
        const int nt = pair & 7;                // ntile-local 0..7
        float2 r;
        r.x = tile[ks * 8 + tg][nt * 8 + gp];
        r.y = tile[ks * 8 + tg + 4][nt * 8 + gp];
        const size_t f = ((size_t)b << 21) + ((size_t)(k0 / 8 + ks) << 13) +
                         ((size_t)(n0 / 8 + nt) << 5) + lane;
        o2[f] = r;
    }
}

// ---------------------------------------------------------------------------
// Kernel C: fragment-packed tf32 mma.sync GEMM + fused bias.
// 8 warps: warp_m(2) x warp_n(4), warp tile 64x32.
// Single-barrier 3-stage mainloop: wait -> sync -> fill(c+2) -> compute(c).
// ---------------------------------------------------------------------------
__global__ void __launch_bounds__(NTHREADS, 2)
gemm_kernel(const int* __restrict__ sel_idx,
            const float* __restrict__ sel_prob,
            const float* __restrict__ bias,
            float* __restrict__ out) {
    extern __shared__ float smem[];
    const int tid = threadIdx.x;
    const int warp = tid >> 5;
    const int lane = tid & 31;
    const int gp = lane >> 2;
    const int tg = lane & 3;
    const int warp_m = warp >> 2;   // 0..1
    const int warp_n = warp & 3;    // 0..3
    const int bz = blockIdx.z;
    const int mt0 = blockIdx.y * (BM / 16);   // base mtile (8 per block)
    const int nt0 = blockIdx.x * (BN / 8);    // base ntile (16 per block)

    if (tid < BN) {
        const int i0 = sel_idx[bz * TOPK + 0];
        const int i1 = sel_idx[bz * TOPK + 1];
        const float p0 = sel_prob[bz * TOPK + 0];
        const float p1 = sel_prob[bz * TOPK + 1];
        const int n0 = blockIdx.x * BN;
        smem[SMEM_BIAS_F + tid] =
            p0 * bias[i0 * DOUT + n0 + tid] + p1 * bias[i1 * DOUT + n0 + tid];
    }

    float acc[4][4][4];
#pragma unroll
    for (int mi = 0; mi < 4; ++mi)
#pragma unroll
        for (int ni = 0; ni < 4; ++ni)
#pragma unroll
            for (int r = 0; r < 4; ++r) acc[mi][ni][r] = 0.0f;

    const uint32_t sbase = (uint32_t)__cvta_generic_to_shared(smem);
    const float4* gA = (const float4*)g_xa + ((size_t)bz << 20);
    const float4* gB = (const float4*)g_wb + ((size_t)bz << 20);

    auto fill = [&](int s, int c) {
#pragma unroll
        for (int i = 0; i < 4; ++i) {
            const int j = tid + i * NTHREADS;        // 0..1023
            const int ks = j >> 8;                   // kslab local 0..3
            const int rem = j & 255;
            const int gks = c * 4 + ks;
            const size_t fa = ((size_t)gks << 12) + ((size_t)(mt0 + (rem >> 5)) << 5) + (rem & 31);
            const uint32_t da = sbase + (uint32_t)((s * STAGE_FLOATS + j * 4) * 4);
            asm volatile("cp.async.cg.shared.global [%0], [%1], 16;"
                         :: "r"(da), "l"(gA + fa));
            const size_t fb = ((size_t)gks << 12) + ((size_t)nt0 << 4) + rem;
            const uint32_t db = sbase + (uint32_t)((s * STAGE_FLOATS + A_STAGE_FLOATS + j * 4) * 4);
            asm volatile("cp.async.cg.shared.global [%0], [%1], 16;"
                         :: "r"(db), "l"(gB + fb));
        }
        asm volatile("cp.async.commit_group;");
    };

    // prologue: fill 2 chunks (one stage stays free for fill-ahead)
    fill(0, 0);
    fill(1, 1);

    for (int c = 0; c < NC; ++c) {
        const int s = c % NSTAGE;
        if (c < NC - 1) asm volatile("cp.async.wait_group 1;" ::: "memory");
        else            asm volatile("cp.async.wait_group 0;" ::: "memory");
        __syncthreads();

        if (c + 2 < NC) fill((c + 2) % NSTAGE, c + 2);  // target = (c-1)%3, freed above

        const float* As = smem + s * STAGE_FLOATS;
        const float* Bs = As + A_STAGE_FLOATS;
#pragma unroll
        for (int ks = 0; ks < 4; ++ks) {
            float a[4][4], bb[4][2];
#pragma unroll
            for (int mi = 0; mi < 4; ++mi) {
                const float4 v = *(const float4*)(As + ks * 1024 +
                                                  (warp_m * 4 + mi) * 128 + lane * 4);
                a[mi][0] = v.x; a[mi][1] = v.y; a[mi][2] = v.z; a[mi][3] = v.w;
            }
#pragma unroll
            for (int ni = 0; ni < 4; ++ni) {
                const float2 v = *(const float2*)(Bs + ks * 1024 +
                                                  (warp_n * 4 + ni) * 64 + lane * 2);
                bb[ni][0] = v.x; bb[ni][1] = v.y;
            }
#pragma unroll
            for (int mi = 0; mi < 4; ++mi)
#pragma unroll
                for (int ni = 0; ni < 4; ++ni)
                    mma_tf32(acc[mi][ni], a[mi], bb[ni]);
        }
    }

    // epilogue: acc + bias, float2 stores (only own registers + const smem read)
    const int m0 = blockIdx.y * BM;
    const int n0 = blockIdx.x * BN;
    float* outb = out + (size_t)bz * SEQ * DOUT + (size_t)m0 * DOUT + n0;
#pragma unroll
    for (int mi = 0; mi < 4; ++mi) {
        const int r0 = warp_m * 64 + mi * 16 + gp;
#pragma unroll
        for (int ni = 0; ni < 4; ++ni) {
            const int cc = warp_n * 32 + ni * 8 + tg * 2;
            const float b0 = smem[SMEM_BIAS_F + cc];
            const float b1 = smem[SMEM_BIAS_F + cc + 1];
            const float2 v0 = make_float2(acc[mi][ni][0] + b0, acc[mi][ni][1] + b1);
            const float2 v1 = make_float2(acc[mi][ni][2] + b0, acc[mi][ni][3] + b1);
            *(float2*)(outb + (size_t)r0 * DOUT + cc) = v0;
            *(float2*)(outb + (size_t)(r0 + 8) * DOUT + cc) = v1;
        }
    }
}

extern "C" void kernel_launch(void* const* d_in, const int* in_sizes, int n_in,
                              void* d_out, int out_size) {
    const float* tensor   = (const float*)d_in[0];  // (B,S,H,Dh) fp32
    const int*   sel_idx  = (const int*)d_in[1];    // (B,TOPK) int32
    const float* sel_prob = (const float*)d_in[2];  // (B,TOPK) fp32
    const float* weight   = (const float*)d_in[3];  // (16,DIN,DOUT) fp32
    const float* bias     = (const float*)d_in[4];  // (16,DOUT) fp32
    float* out = (float*)d_out;

    {
        dim3 g(SEQ / 64, DIN / 64, BATCH);
        pack_x_kernel<<<g, 256>>>(tensor);
    }
    {
        dim3 g(DIN / 64, DOUT / 64, BATCH);
        pack_w_kernel<<<g, 256>>>(sel_idx, sel_prob, weight);
    }

    cudaFuncSetAttribute(gemm_kernel,
                         cudaFuncAttributeMaxDynamicSharedMemorySize, SMEM_BYTES);
    dim3 grid(DOUT / BN, SEQ / BM, BATCH);
    gemm_kernel<<<grid, NTHREADS, SMEM_BYTES>>>(sel_idx, sel_prob, bias, out);
}

// round 7
// speedup vs baseline: 1.2716x; 1.0297x over previous
#include <cuda_runtime.h>
#include <cstdint>

#define BATCH 2
#define SEQ 2048
#define DIN 2048
#define DOUT 2048
#define TOPK 2

#define BM 128
#define BN 256
#define BK 32
#define NC (DIN / BK)          // 64 k-chunks
#define NSTAGE 4
#define NTHREADS 256

// stage = A(4096 floats) + B(8192 floats) = 48KB
#define A_STAGE_FLOATS 4096
#define STAGE_FLOATS 12288
#define SMEM_BIAS_F (NSTAGE * STAGE_FLOATS)            // 49152 floats
#define SMEM_FLOATS (SMEM_BIAS_F + BN)
#define SMEM_BYTES  (SMEM_FLOATS * 4)                  // 197632

// Fragment-packed scratch (__device__ globals: allocation-guard-safe).
// A: [b][kslab(256)][mtile(128)][lane(32)][4]   (float4 per lane)
// B: [b][kslab(256)][ntile(256)][lane(32)][2]   (float2 per lane)
__device__ __align__(16) float g_xa[(size_t)BATCH * SEQ * DIN];
__device__ __align__(16) float g_wb[(size_t)BATCH * DIN * DOUT];

__device__ __forceinline__ float to_tf32(float v) {
    uint32_t u;
    asm("cvt.rna.tf32.f32 %0, %1;" : "=r"(u) : "f"(v));
    return __uint_as_float(u);
}

__device__ __forceinline__ void mma_tf32(float c[4], const float a[4], const float b[2]) {
    const uint32_t* A = reinterpret_cast<const uint32_t*>(a);
    const uint32_t* B = reinterpret_cast<const uint32_t*>(b);
    asm volatile(
        "mma.sync.aligned.m16n8k8.row.col.f32.tf32.tf32.f32 "
        "{%0,%1,%2,%3}, {%4,%5,%6,%7}, {%8,%9}, {%0,%1,%2,%3};\n"
        : "+f"(c[0]), "+f"(c[1]), "+f"(c[2]), "+f"(c[3])
        : "r"(A[0]), "r"(A[1]), "r"(A[2]), "r"(A[3]), "r"(B[0]), "r"(B[1]));
}

// ---------------------------------------------------------------------------
// Fused pack kernel: blockIdx.x < 32 -> pack X tile; else -> pack W tile.
// Both halves: coalesced float4 loads -> smem tile[64][72] -> fragment stores.
// Fusing overlaps the two passes (they serialized as separate launches).
// ---------------------------------------------------------------------------
__global__ void pack_kernel(const float* __restrict__ x,
                            const int* __restrict__ sel_idx,
                            const float* __restrict__ sel_prob,
                            const float* __restrict__ weight) {
    __shared__ float tile[64][72];
    const int b = blockIdx.z;
    const int tid = threadIdx.x;
    const int warp = tid >> 5;
    const int lane = tid & 31;
    const int gp = lane >> 2, tg = lane & 3;

    if (blockIdx.x < 32) {
        // ---- X: 64 m-rows x 64 k-cols ----
        const int m0 = blockIdx.x * 64;
        const int k0 = blockIdx.y * 64;
        const float* xb = x + ((size_t)b * SEQ + m0) * DIN + k0;
#pragma unroll
        for (int i = 0; i < 4; ++i) {
            const int idx = tid + i * 256;
            const int r = idx >> 4;
            const int c4 = (idx & 15) << 2;
            const float4 v = *(const float4*)(xb + (size_t)r * DIN + c4);
            tile[r][c4 + 0] = to_tf32(v.x);
            tile[r][c4 + 1] = to_tf32(v.y);
            tile[r][c4 + 2] = to_tf32(v.z);
            tile[r][c4 + 3] = to_tf32(v.w);
        }
        __syncthreads();
        float4* o4 = (float4*)g_xa;
#pragma unroll
        for (int i = 0; i < 4; ++i) {
            const int pair = warp * 4 + i;          // 0..31
            const int mt = pair >> 3;               // mtile-local 0..3
            const int ks = pair & 7;                // kslab-local 0..7
            float4 r;
            r.x = tile[mt * 16 + gp][ks * 8 + tg];
            r.y = tile[mt * 16 + gp + 8][ks * 8 + tg];
            r.z = tile[mt * 16 + gp][ks * 8 + tg + 4];
            r.w = tile[mt * 16 + gp + 8][ks * 8 + tg + 4];
            const size_t f = ((size_t)b << 20) + ((size_t)(k0 / 8 + ks) << 12) +
                             ((size_t)(m0 / 16 + mt) << 5) + lane;
            o4[f] = r;
        }
    } else {
        // ---- W: superpose + pack, 64 k-rows x 64 n-cols ----
        const int k0 = (blockIdx.x - 32) * 64;
        const int n0 = blockIdx.y * 64;
        const int i0 = sel_idx[b * TOPK + 0];
        const int i1 = sel_idx[b * TOPK + 1];
        const float p0 = sel_prob[b * TOPK + 0];
        const float p1 = sel_prob[b * TOPK + 1];
        const float* w0 = weight + (size_t)i0 * DIN * DOUT + (size_t)k0 * DOUT + n0;
        const float* w1 = weight + (size_t)i1 * DIN * DOUT + (size_t)k0 * DOUT + n0;
#pragma unroll
        for (int i = 0; i < 4; ++i) {
            const int idx = tid + i * 256;
            const int r = idx >> 4;
            const int c4 = (idx & 15) << 2;
            const float4 va = *(const float4*)(w0 + (size_t)r * DOUT + c4);
            const float4 vb = *(const float4*)(w1 + (size_t)r * DOUT + c4);
            tile[r][c4 + 0] = to_tf32(p0 * va.x + p1 * vb.x);
            tile[r][c4 + 1] = to_tf32(p0 * va.y + p1 * vb.y);
            tile[r][c4 + 2] = to_tf32(p0 * va.z + p1 * vb.z);
            tile[r][c4 + 3] = to_tf32(p0 * va.w + p1 * vb.w);
        }
        __syncthreads();
        float2* o2 = (float2*)g_wb;
#pragma unroll
        for (int i = 0; i < 8; ++i) {
            const int pair = warp * 8 + i;          // 0..63
            const int ks = pair >> 3;               // kslab-local 0..7
            const int nt = pair & 7;                // ntile-local 0..7
            float2 r;
            r.x = tile[ks * 8 + tg][nt * 8 + gp];
            r.y = tile[ks * 8 + tg + 4][nt * 8 + gp];
            const size_t f = ((size_t)b << 21) + ((size_t)(k0 / 8 + ks) << 13) +
                             ((size_t)(n0 / 8 + nt) << 5) + lane;
            o2[f] = r;
        }
    }
}

// ---------------------------------------------------------------------------
// GEMM: BM=128 x BN=256, BK=32, 4-stage cp.async, 8 warps of 64x64.
// Single barrier per chunk; fill(c+3) issued before the MMA burst.
// ---------------------------------------------------------------------------
__global__ void __launch_bounds__(NTHREADS, 1)
gemm_kernel(const int* __restrict__ sel_idx,
            const float* __restrict__ sel_prob,
            const float* __restrict__ bias,
            float* __restrict__ out) {
    extern __shared__ float smem[];
    const int tid = threadIdx.x;
    const int warp = tid >> 5;
    const int lane = tid & 31;
    const int gp = lane >> 2;
    const int tg = lane & 3;
    const int warp_m = warp >> 2;   // 0..1  (64-row slab)
    const int warp_n = warp & 3;    // 0..3  (64-col slab)
    const int bz = blockIdx.z;
    const int mt0 = blockIdx.y * (BM / 16);   // 8 mtiles per block
    const int nt0 = blockIdx.x * (BN / 8);    // 32 ntiles per block

    {
        const int i0 = sel_idx[bz * TOPK + 0];
        const int i1 = sel_idx[bz * TOPK + 1];
        const float p0 = sel_prob[bz * TOPK + 0];
        const float p1 = sel_prob[bz * TOPK + 1];
        const int n0 = blockIdx.x * BN;
        smem[SMEM_BIAS_F + tid] =
            p0 * bias[i0 * DOUT + n0 + tid] + p1 * bias[i1 * DOUT + n0 + tid];
    }

    float acc[4][8][4];
#pragma unroll
    for (int mi = 0; mi < 4; ++mi)
#pragma unroll
        for (int ni = 0; ni < 8; ++ni)
#pragma unroll
            for (int r = 0; r < 4; ++r) acc[mi][ni][r] = 0.0f;

    const uint32_t sbase = (uint32_t)__cvta_generic_to_shared(smem);
    const float4* gA = (const float4*)g_xa + ((size_t)bz << 20);
    const float4* gB = (const float4*)g_wb + ((size_t)bz << 20);

    auto fill = [&](int s, int c) {
        // A: 1024 float4, 4/thread, 128B-contiguous runs per (kslab, 8 mtiles)
#pragma unroll
        for (int i = 0; i < 4; ++i) {
            const int j = tid + i * NTHREADS;        // 0..1023
            const int ks = j >> 8;                   // kslab-local 0..3
            const int rem = j & 255;
            const int gks = c * 4 + ks;
            const size_t fa = ((size_t)gks << 12) +
                              ((size_t)(mt0 + (rem >> 5)) << 5) + (rem & 31);
            const uint32_t da = sbase + (uint32_t)((s * STAGE_FLOATS + j * 4) * 4);
            asm volatile("cp.async.cg.shared.global [%0], [%1], 16;"
                         :: "r"(da), "l"(gA + fa));
        }
        // B: 2048 float4, 8/thread, 512-float4 contiguous runs per kslab
#pragma unroll
        for (int i = 0; i < 8; ++i) {
            const int j = tid + i * NTHREADS;        // 0..2047
            const int ks = j >> 9;                   // kslab-local 0..3
            const int rem = j & 511;
            const int gks = c * 4 + ks;
            const size_t fb = ((size_t)gks << 12) + ((size_t)nt0 << 4) + rem;
            const uint32_t db = sbase +
                (uint32_t)((s * STAGE_FLOATS + A_STAGE_FLOATS + j * 4) * 4);
            asm volatile("cp.async.cg.shared.global [%0], [%1], 16;"
                         :: "r"(db), "l"(gB + fb));
        }
        asm volatile("cp.async.commit_group;");
    };

    fill(0, 0);
    fill(1, 1);
    fill(2, 2);

    for (int c = 0; c < NC; ++c) {
        const int s = c % NSTAGE;
        const int pend = (NC - 1 - c) < 2 ? (NC - 1 - c) : 2;
        if (pend == 2)      asm volatile("cp.async.wait_group 2;" ::: "memory");
        else if (pend == 1) asm volatile("cp.async.wait_group 1;" ::: "memory");
        else                asm volatile("cp.async.wait_group 0;" ::: "memory");
        __syncthreads();

        if (c + 3 < NC) fill((c + 3) % NSTAGE, c + 3);

        const float* As = smem + s * STAGE_FLOATS;
        const float* Bs = As + A_STAGE_FLOATS;
#pragma unroll
        for (int ks = 0; ks < 4; ++ks) {
            float a[4][4], bb[8][2];
#pragma unroll
            for (int mi = 0; mi < 4; ++mi) {
                const float4 v = *(const float4*)(As + ks * 1024 +
                                                  (warp_m * 4 + mi) * 128 + lane * 4);
                a[mi][0] = v.x; a[mi][1] = v.y; a[mi][2] = v.z; a[mi][3] = v.w;
            }
#pragma unroll
            for (int ni = 0; ni < 8; ++ni) {
                const float2 v = *(const float2*)(Bs + ks * 2048 +
                                                  (warp_n * 8 + ni) * 64 + lane * 2);
                bb[ni][0] = v.x; bb[ni][1] = v.y;
            }
#pragma unroll
            for (int mi = 0; mi < 4; ++mi)
#pragma unroll
                for (int ni = 0; ni < 8; ++ni)
                    mma_tf32(acc[mi][ni], a[mi], bb[ni]);
        }
    }

    // epilogue: acc + bias, float2 stores
    const int m0 = blockIdx.y * BM;
    const int n0 = blockIdx.x * BN;
    float* outb = out + (size_t)bz * SEQ * DOUT + (size_t)m0 * DOUT + n0;
#pragma unroll
    for (int mi = 0; mi < 4; ++mi) {
        const int r0 = warp_m * 64 + mi * 16 + gp;
#pragma unroll
        for (int ni = 0; ni < 8; ++ni) {
            const int cc = warp_n * 64 + ni * 8 + tg * 2;
            const float b0 = smem[SMEM_BIAS_F + cc];
            const float b1 = smem[SMEM_BIAS_F + cc + 1];
            const float2 v0 = make_float2(acc[mi][ni][0] + b0, acc[mi][ni][1] + b1);
            const float2 v1 = make_float2(acc[mi][ni][2] + b0, acc[mi][ni][3] + b1);
            *(float2*)(outb + (size_t)r0 * DOUT + cc) = v0;
            *(float2*)(outb + (size_t)(r0 + 8) * DOUT + cc) = v1;
        }
    }
}

extern "C" void kernel_launch(void* const* d_in, const int* in_sizes, int n_in,
                              void* d_out, int out_size) {
    const float* tensor   = (const float*)d_in[0];  // (B,S,H,Dh) fp32
    const int*   sel_idx  = (const int*)d_in[1];    // (B,TOPK) int32
    const float* sel_prob = (const float*)d_in[2];  // (B,TOPK) fp32
    const float* weight   = (const float*)d_in[3];  // (16,DIN,DOUT) fp32
    const float* bias     = (const float*)d_in[4];  // (16,DOUT) fp32
    float* out = (float*)d_out;

    {
        dim3 g(64, 32, BATCH);   // x<32: pack X, x>=32: pack W
        pack_kernel<<<g, 256>>>(tensor, sel_idx, sel_prob, weight);
    }

    cudaFuncSetAttribute(gemm_kernel,
                         cudaFuncAttributeMaxDynamicSharedMemorySize, SMEM_BYTES);
    dim3 grid(DOUT / BN, SEQ / BM, BATCH);
    gemm_kernel<<<grid, NTHREADS, SMEM_BYTES>>>(sel_idx, sel_prob, bias, out);
}